// round 4
// baseline (speedup 1.0000x reference)
#include <cuda_runtime.h>
#include <cstdint>
#include <math.h>

// LSTM: B=128, S=1024, I=512, H=1024, O=128
#define S_LEN 1024
#define BATCH 128
#define IDIM  512
#define HDIM  1024
#define GDIM  4096
#define ODIM  128
#define NCTA  128

// ---------------- scratch (static device allocations; no cudaMalloc) ----------------
__device__ float g_x  [(size_t)BATCH * S_LEN * IDIM];   // tf32-rounded copy of x (256 MB)
__device__ float g_Wx [(size_t)GDIM * IDIM];            // tf32-rounded Wx (8 MB)
__device__ float g_xg0[(size_t)65536 * GDIM];           // xg rows m <  65536 (1 GiB)
__device__ float g_xg1[(size_t)65536 * GDIM];           // xg rows m >= 65536 (1 GiB)
__device__ float g_h0 [BATCH * HDIM];
__device__ float g_h1 [BATCH * HDIM];
__device__ unsigned g_bar;                              // monotone grid-barrier counter

// ---------------- helpers ----------------
__device__ __forceinline__ uint32_t f2b(float x) { return __float_as_uint(x); }

__device__ __forceinline__ float tf32_rna(float v) {
    uint32_t u;
    asm("cvt.rna.tf32.f32 %0, %1;" : "=r"(u) : "f"(v));
    return __uint_as_float(u);
}

__device__ __forceinline__ void cp16(void* sptr, const void* gptr) {
    uint32_t s = (uint32_t)__cvta_generic_to_shared(sptr);
    asm volatile("cp.async.cg.shared.global [%0], [%1], 16;\n" :: "r"(s), "l"(gptr));
}
__device__ __forceinline__ void cp_commit() { asm volatile("cp.async.commit_group;\n"); }
template <int N> __device__ __forceinline__ void cp_wait() {
    asm volatile("cp.async.wait_group %0;\n" :: "n"(N));
}

// D += A(16x8) * B(8x8), tf32 inputs, fp32 accumulate
__device__ __forceinline__ void mma_tf32(float* d, const uint32_t* a, uint32_t b0, uint32_t b1) {
    asm volatile(
        "mma.sync.aligned.m16n8k8.row.col.f32.tf32.tf32.f32 "
        "{%0,%1,%2,%3},{%4,%5,%6,%7},{%8,%9},{%0,%1,%2,%3};\n"
        : "+f"(d[0]), "+f"(d[1]), "+f"(d[2]), "+f"(d[3])
        : "r"(a[0]), "r"(a[1]), "r"(a[2]), "r"(a[3]), "r"(b0), "r"(b1));
}

__device__ __forceinline__ float sigf(float x) { return 1.0f / (1.0f + expf(-x)); }

// Software grid barrier: monotone counter, wrap-safe compare, no reset needed
// across graph replays. Safe because all NCTA CTAs are co-resident (1 CTA/SM,
// grid=128 <= 148 SMs).
__device__ __forceinline__ void grid_barrier() {
    __threadfence();           // make this thread's h stores visible at GPU scope
    __syncthreads();           // all threads of CTA arrived (stores issued + fenced)
    if (threadIdx.x == 0) {
        unsigned ticket = atomicAdd(&g_bar, 1u) + 1u;
        unsigned target = (ticket + (NCTA - 1u)) & ~(NCTA - 1u);
        unsigned v;
        do { v = *((volatile unsigned*)&g_bar); } while ((int)(v - target) < 0);
    }
    __syncthreads();
}

// ---------------- prep: round x, Wx to tf32 once per call ----------------
__global__ void prep_kernel(const float* __restrict__ x,
                            const float* __restrict__ Wx) {
    const size_t NX  = (size_t)BATCH * S_LEN * IDIM / 4;  // 16777216 float4
    const size_t NWX = (size_t)GDIM * IDIM / 4;           // 524288
    size_t i = (size_t)blockIdx.x * blockDim.x + threadIdx.x;
    if (i >= NX + NWX) return;
    const float4* src; float4* dst; size_t j;
    if (i < NX) { src = (const float4*)x;  dst = (float4*)g_x;  j = i; }
    else        { src = (const float4*)Wx; dst = (float4*)g_Wx; j = i - NX; }
    float4 v = src[j];
    v.x = tf32_rna(v.x); v.y = tf32_rna(v.y);
    v.z = tf32_rna(v.z); v.w = tf32_rna(v.w);
    dst[j] = v;
}

// ---------------- kernel A: xg = x @ Wx^T + (bW + bU) ----------------
// tile 128x128, BK=32, 256 threads (8 warps = 4M x 2N), double-buffered cp.async
#define LDA 36
__global__ __launch_bounds__(256) void gemm_xg_kernel(const float* __restrict__ bW,
                                                      const float* __restrict__ bU) {
    extern __shared__ float sm[];
    float* As = sm;                   // 2 stages * 128*LDA
    float* Bs = sm + 2 * 128 * LDA;   // 2 stages * 128*LDA
    const int n0 = blockIdx.x * 128;
    const int m0 = blockIdx.y * 128;
    const float* Ag = g_x  + (size_t)m0 * IDIM;
    const float* Bg = g_Wx + (size_t)n0 * IDIM;
    const int tid = threadIdx.x, lane = tid & 31, wid = tid >> 5;
    const int wm = wid >> 1, wn = wid & 1;  // warp tile: 32 rows x 64 cols

    float acc[2][8][4];
#pragma unroll
    for (int a = 0; a < 2; a++)
#pragma unroll
        for (int b = 0; b < 8; b++)
#pragma unroll
            for (int c = 0; c < 4; c++) acc[a][b][c] = 0.0f;

    auto load = [&](int kb, int st) {
        float* Ad = As + st * 128 * LDA;
        float* Bd = Bs + st * 128 * LDA;
#pragma unroll
        for (int i = 0; i < 4; i++) {
            int f = tid + i * 256, r = f >> 3, kq = f & 7;
            cp16(Ad + r * LDA + kq * 4, Ag + (size_t)r * IDIM + kb * 32 + kq * 4);
        }
#pragma unroll
        for (int i = 0; i < 4; i++) {
            int f = tid + i * 256, r = f >> 3, kq = f & 7;
            cp16(Bd + r * LDA + kq * 4, Bg + (size_t)r * IDIM + kb * 32 + kq * 4);
        }
        cp_commit();
    };

    load(0, 0);
    const int NKB = IDIM / 32;  // 16
    for (int kb = 0; kb < NKB; kb++) {
        int st = kb & 1;
        if (kb + 1 < NKB) { load(kb + 1, st ^ 1); cp_wait<1>(); }
        else              { cp_wait<0>(); }
        __syncthreads();
        const float* A = As + st * 128 * LDA;
        const float* B = Bs + st * 128 * LDA;
#pragma unroll
        for (int k8 = 0; k8 < 4; k8++) {
            int kk = k8 * 8;
            uint32_t a[2][4];
#pragma unroll
            for (int mf = 0; mf < 2; mf++) {
                int r = wm * 32 + mf * 16 + (lane >> 2);
                int c = kk + (lane & 3);
                a[mf][0] = f2b(A[r * LDA + c]);
                a[mf][1] = f2b(A[(r + 8) * LDA + c]);
                a[mf][2] = f2b(A[r * LDA + c + 4]);
                a[mf][3] = f2b(A[(r + 8) * LDA + c + 4]);
            }
#pragma unroll
            for (int nf = 0; nf < 8; nf++) {
                int br = wn * 64 + nf * 8 + (lane >> 2);
                int bc = kk + (lane & 3);
                uint32_t b0 = f2b(B[br * LDA + bc]);
                uint32_t b1 = f2b(B[br * LDA + bc + 4]);
                mma_tf32(acc[0][nf], a[0], b0, b1);
                mma_tf32(acc[1][nf], a[1], b0, b1);
            }
        }
        __syncthreads();
    }

    float* out; int mloc;
    if (m0 < 65536) { out = g_xg0; mloc = m0; } else { out = g_xg1; mloc = m0 - 65536; }
#pragma unroll
    for (int mf = 0; mf < 2; mf++)
#pragma unroll
        for (int nf = 0; nf < 8; nf++) {
            int r = mloc + wm * 32 + mf * 16 + (lane >> 2);
            int c = n0 + wn * 64 + nf * 8 + (lane & 3) * 2;
            float bi0 = bW[c] + bU[c];
            float bi1 = bW[c + 1] + bU[c + 1];
            out[(size_t)r * GDIM + c]           = acc[mf][nf][0] + bi0;
            out[(size_t)r * GDIM + c + 1]       = acc[mf][nf][1] + bi1;
            out[(size_t)(r + 8) * GDIM + c]     = acc[mf][nf][2] + bi0;
            out[(size_t)(r + 8) * GDIM + c + 1] = acc[mf][nf][3] + bi1;
        }
}

// ---------------- persistent recurrence kernel ----------------
// 128 CTAs, all co-resident. CTA n owns hidden cols [n*8, n*8+8). Its 32x1024
// Wh tile (4 gates x 8 cols) lives in SMEM (tf32) for all 1024 steps. c lives
// in registers. Per step: stream h (128x1024) through a double-buffered SMEM
// stage, 128x32 tf32 MMA, elementwise cell update, software grid barrier.
#define LDW 1028   // Wh smem row stride (mod 32 == 4 -> conflict-free B-frag LDS)
#define LDB 68     // h  smem row stride (mod 32 == 4 -> conflict-free A-frag LDS)
#define SM_WH (32 * LDW)            // 32896 floats = 131584 B
#define SM_AS (2 * 128 * LDB)       // 17408 floats =  69632 B
#define SMEM_STEP ((SM_WH + SM_AS) * 4)  // 201216 B

__global__ __launch_bounds__(256, 1) void lstm_persistent_kernel(const float* __restrict__ Wh) {
    extern __shared__ float sm[];
    float* Bw = sm;            // [32][LDW] persistent Wh tile (tf32)
    float* As = sm + SM_WH;    // 2 stages * [128][LDB] h staging; reused as G stash
    const int j0 = blockIdx.x * 8;
    const int tid = threadIdx.x, lane = tid & 31, wid = tid >> 5;

    // one-time: gather this CTA's 32 Wh rows (row q*1024 + j0+jj), tf32-round
    for (int idx = tid; idx < 32 * 1024; idx += 256) {
        int r = idx >> 10, c = idx & 1023;              // r = q*8 + jj
        int wr = (r >> 3) * HDIM + j0 + (r & 7);
        Bw[r * LDW + c] = tf32_rna(Wh[(size_t)wr * HDIM + c]);
    }
    float creg[4] = {0.0f, 0.0f, 0.0f, 0.0f};
    __syncthreads();

    for (int t = 0; t < S_LEN; t++) {
        const float* h_in  = (t & 1) ? g_h1 : g_h0;
        float*       h_out = (t & 1) ? g_h0 : g_h1;

        float acc[4][4];
#pragma unroll
        for (int a = 0; a < 4; a++)
#pragma unroll
            for (int b = 0; b < 4; b++) acc[a][b] = 0.0f;

        if (t > 0) {  // t==0: h==0 -> gates are xg only
            auto load = [&](int kb, int st) {
                float* Ad = As + st * 128 * LDB;
#pragma unroll
                for (int i = 0; i < 8; i++) {
                    int f = tid + i * 256, r = f >> 4, kq = f & 15;
                    cp16(Ad + r * LDB + kq * 4, h_in + r * HDIM + kb * 64 + kq * 4);
                }
                cp_commit();
            };
            load(0, 0);
            const int NKB = HDIM / 64;  // 16
            for (int kb = 0; kb < NKB; kb++) {
                int st = kb & 1;
                if (kb + 1 < NKB) { load(kb + 1, st ^ 1); cp_wait<1>(); }
                else              { cp_wait<0>(); }
                __syncthreads();
                const float* A = As + st * 128 * LDB;
#pragma unroll
                for (int k8 = 0; k8 < 8; k8++) {
                    int kk = k8 * 8;
                    int r  = wid * 16 + (lane >> 2);
                    int cA = kk + (lane & 3);
                    uint32_t a[4];
                    a[0] = f2b(A[r * LDB + cA]);
                    a[1] = f2b(A[(r + 8) * LDB + cA]);
                    a[2] = f2b(A[r * LDB + cA + 4]);
                    a[3] = f2b(A[(r + 8) * LDB + cA + 4]);
                    int cB = kb * 64 + kk + (lane & 3);
#pragma unroll
                    for (int nf = 0; nf < 4; nf++) {
                        int br = nf * 8 + (lane >> 2);
                        uint32_t b0 = f2b(Bw[br * LDW + cB]);
                        uint32_t b1 = f2b(Bw[br * LDW + cB + 4]);
                        mma_tf32(acc[nf], a, b0, b1);
                    }
                }
                __syncthreads();
            }
        }

        // stash gate tile (h@Wh part) into smem (reuse As region)
        float* G = As;  // [128][33]
#pragma unroll
        for (int nf = 0; nf < 4; nf++) {
            int r = wid * 16 + (lane >> 2);
            int c = nf * 8 + (lane & 3) * 2;
            G[r * 33 + c]           = acc[nf][0];
            G[r * 33 + c + 1]       = acc[nf][1];
            G[(r + 8) * 33 + c]     = acc[nf][2];
            G[(r + 8) * 33 + c + 1] = acc[nf][3];
        }
        __syncthreads();

        // elementwise LSTM cell update for this CTA's 128 x 8 block, c in regs
#pragma unroll
        for (int i = 0; i < 4; i++) {
            int e = tid + i * 256;
            int b = e >> 3, jj = e & 7;
            const float* xgp; int mloc;
            if (b < 64) { xgp = g_xg0; mloc = b * 1024 + t; }
            else        { xgp = g_xg1; mloc = (b - 64) * 1024 + t; }
            size_t xb = (size_t)mloc * GDIM + j0 + jj;
            float fg = G[b * 33 + jj]      + xgp[xb];
            float ig = G[b * 33 + 8 + jj]  + xgp[xb + 1024];
            float gg = G[b * 33 + 16 + jj] + xgp[xb + 2048];
            float og = G[b * 33 + 24 + jj] + xgp[xb + 3072];
            float cn = sigf(fg) * creg[i] + sigf(ig) * tanhf(gg);
            creg[i] = cn;
            // pre-round: next step's A operand is consumed as tf32 anyway
            h_out[b * HDIM + j0 + jj] = tf32_rna(sigf(og) * tanhf(cn));
        }

        grid_barrier();
    }
}

// ---------------- FC head: out = hT @ fc_w^T + fc_b ----------------
__global__ void fc_kernel(const float* __restrict__ fc_w,
                          const float* __restrict__ fc_b,
                          float* __restrict__ out) {
    __shared__ float hrow[HDIM];
    int b = blockIdx.x, o = threadIdx.x;
    for (int k = o; k < HDIM; k += 128) hrow[k] = g_h0[b * HDIM + k];
    __syncthreads();
    const float* w = fc_w + (size_t)o * HDIM;
    float acc = fc_b[o];
#pragma unroll 8
    for (int k = 0; k < HDIM; k++) acc += hrow[k] * w[k];
    out[b * ODIM + o] = acc;
}

// ---------------- launch ----------------
extern "C" void kernel_launch(void* const* d_in, const int* in_sizes, int n_in,
                              void* d_out, int out_size) {
    const float* x    = (const float*)d_in[0];
    const float* Wx   = (const float*)d_in[1];
    const float* bW   = (const float*)d_in[2];
    const float* Wh   = (const float*)d_in[3];
    const float* bU   = (const float*)d_in[4];
    const float* fc_w = (const float*)d_in[5];
    const float* fc_b = (const float*)d_in[6];
    float* out = (float*)d_out;

    // opt-in to >48KB dynamic smem (state change, idempotent, no allocation)
    cudaFuncSetAttribute(gemm_xg_kernel, cudaFuncAttributeMaxDynamicSharedMemorySize, 73728);
    cudaFuncSetAttribute(lstm_persistent_kernel, cudaFuncAttributeMaxDynamicSharedMemorySize, SMEM_STEP);

    prep_kernel<<<67584, 256>>>(x, Wx);
    gemm_xg_kernel<<<dim3(32, 1024), 256, 73728>>>(bW, bU);
    lstm_persistent_kernel<<<NCTA, 256, SMEM_STEP>>>(Wh);
    fc_kernel<<<128, 128>>>(fc_w, fc_b, out);
}

// round 5
// speedup vs baseline: 1.4579x; 1.4579x over previous
#include <cuda_runtime.h>
#include <cstdint>
#include <math.h>

// LSTM: B=128, S=1024, I=512, H=1024, O=128
#define S_LEN 1024
#define BATCH 128
#define IDIM  512
#define HDIM  1024
#define GDIM  4096
#define ODIM  128
#define NCTA  128

// ---------------- scratch (static device allocations; no cudaMalloc) ----------------
__device__ float g_x  [(size_t)BATCH * S_LEN * IDIM];   // tf32-rounded copy of x (256 MB)
__device__ float g_Wx [(size_t)GDIM * IDIM];            // tf32-rounded Wx (8 MB)
__device__ float g_xg0[(size_t)65536 * GDIM];           // xg rows m <  65536 (1 GiB)
__device__ float g_xg1[(size_t)65536 * GDIM];           // xg rows m >= 65536 (1 GiB)
__device__ float g_h0 [BATCH * HDIM];
__device__ float g_h1 [BATCH * HDIM];
__device__ unsigned g_bar;                              // monotone grid-barrier counter

// ---------------- helpers ----------------
__device__ __forceinline__ uint32_t f2b(float x) { return __float_as_uint(x); }

__device__ __forceinline__ float tf32_rna(float v) {
    uint32_t u;
    asm("cvt.rna.tf32.f32 %0, %1;" : "=r"(u) : "f"(v));
    return __uint_as_float(u);
}

__device__ __forceinline__ void cp16(void* sptr, const void* gptr) {
    uint32_t s = (uint32_t)__cvta_generic_to_shared(sptr);
    asm volatile("cp.async.cg.shared.global [%0], [%1], 16;\n" :: "r"(s), "l"(gptr));
}
__device__ __forceinline__ void cp_commit() { asm volatile("cp.async.commit_group;\n"); }
template <int N> __device__ __forceinline__ void cp_wait() {
    asm volatile("cp.async.wait_group %0;\n" :: "n"(N));
}

// D += A(16x8) * B(8x8), tf32 inputs, fp32 accumulate
__device__ __forceinline__ void mma_tf32(float* d, const uint32_t* a, uint32_t b0, uint32_t b1) {
    asm volatile(
        "mma.sync.aligned.m16n8k8.row.col.f32.tf32.tf32.f32 "
        "{%0,%1,%2,%3},{%4,%5,%6,%7},{%8,%9},{%0,%1,%2,%3};\n"
        : "+f"(d[0]), "+f"(d[1]), "+f"(d[2]), "+f"(d[3])
        : "r"(a[0]), "r"(a[1]), "r"(a[2]), "r"(a[3]), "r"(b0), "r"(b1));
}

__device__ __forceinline__ float sigf(float x) { return 1.0f / (1.0f + expf(-x)); }

// Software grid barrier: monotone counter, wrap-safe compare, no reset needed
// across graph replays. Safe because all NCTA CTAs are co-resident (1 CTA/SM,
// grid=128 <= 148 SMs).
__device__ __forceinline__ void grid_barrier() {
    __threadfence();           // make this thread's h stores visible at GPU scope
    __syncthreads();           // all threads of CTA arrived (stores issued + fenced)
    if (threadIdx.x == 0) {
        unsigned ticket = atomicAdd(&g_bar, 1u) + 1u;
        unsigned target = (ticket + (NCTA - 1u)) & ~(NCTA - 1u);
        unsigned v;
        do { v = *((volatile unsigned*)&g_bar); } while ((int)(v - target) < 0);
    }
    __syncthreads();
}

// ---------------- prep: round x, Wx to tf32 once per call ----------------
__global__ void prep_kernel(const float* __restrict__ x,
                            const float* __restrict__ Wx) {
    const size_t NX  = (size_t)BATCH * S_LEN * IDIM / 4;  // 16777216 float4
    const size_t NWX = (size_t)GDIM * IDIM / 4;           // 524288
    size_t i = (size_t)blockIdx.x * blockDim.x + threadIdx.x;
    if (i >= NX + NWX) return;
    const float4* src; float4* dst; size_t j;
    if (i < NX) { src = (const float4*)x;  dst = (float4*)g_x;  j = i; }
    else        { src = (const float4*)Wx; dst = (float4*)g_Wx; j = i - NX; }
    float4 v = src[j];
    v.x = tf32_rna(v.x); v.y = tf32_rna(v.y);
    v.z = tf32_rna(v.z); v.w = tf32_rna(v.w);
    dst[j] = v;
}

// ---------------- kernel A: xg = x @ Wx^T + (bW + bU) ----------------
// tile 128x128, BK=32, 256 threads (8 warps = 4M x 2N), double-buffered cp.async
#define LDA 36
__global__ __launch_bounds__(256) void gemm_xg_kernel(const float* __restrict__ bW,
                                                      const float* __restrict__ bU) {
    extern __shared__ float sm[];
    float* As = sm;                   // 2 stages * 128*LDA
    float* Bs = sm + 2 * 128 * LDA;   // 2 stages * 128*LDA
    const int n0 = blockIdx.x * 128;
    const int m0 = blockIdx.y * 128;
    const float* Ag = g_x  + (size_t)m0 * IDIM;
    const float* Bg = g_Wx + (size_t)n0 * IDIM;
    const int tid = threadIdx.x, lane = tid & 31, wid = tid >> 5;
    const int wm = wid >> 1, wn = wid & 1;  // warp tile: 32 rows x 64 cols

    float acc[2][8][4];
#pragma unroll
    for (int a = 0; a < 2; a++)
#pragma unroll
        for (int b = 0; b < 8; b++)
#pragma unroll
            for (int c = 0; c < 4; c++) acc[a][b][c] = 0.0f;

    auto load = [&](int kb, int st) {
        float* Ad = As + st * 128 * LDA;
        float* Bd = Bs + st * 128 * LDA;
#pragma unroll
        for (int i = 0; i < 4; i++) {
            int f = tid + i * 256, r = f >> 3, kq = f & 7;
            cp16(Ad + r * LDA + kq * 4, Ag + (size_t)r * IDIM + kb * 32 + kq * 4);
        }
#pragma unroll
        for (int i = 0; i < 4; i++) {
            int f = tid + i * 256, r = f >> 3, kq = f & 7;
            cp16(Bd + r * LDA + kq * 4, Bg + (size_t)r * IDIM + kb * 32 + kq * 4);
        }
        cp_commit();
    };

    load(0, 0);
    const int NKB = IDIM / 32;  // 16
    for (int kb = 0; kb < NKB; kb++) {
        int st = kb & 1;
        if (kb + 1 < NKB) { load(kb + 1, st ^ 1); cp_wait<1>(); }
        else              { cp_wait<0>(); }
        __syncthreads();
        const float* A = As + st * 128 * LDA;
        const float* B = Bs + st * 128 * LDA;
#pragma unroll
        for (int k8 = 0; k8 < 4; k8++) {
            int kk = k8 * 8;
            uint32_t a[2][4];
#pragma unroll
            for (int mf = 0; mf < 2; mf++) {
                int r = wm * 32 + mf * 16 + (lane >> 2);
                int c = kk + (lane & 3);
                a[mf][0] = f2b(A[r * LDA + c]);
                a[mf][1] = f2b(A[(r + 8) * LDA + c]);
                a[mf][2] = f2b(A[r * LDA + c + 4]);
                a[mf][3] = f2b(A[(r + 8) * LDA + c + 4]);
            }
#pragma unroll
            for (int nf = 0; nf < 8; nf++) {
                int br = wn * 64 + nf * 8 + (lane >> 2);
                int bc = kk + (lane & 3);
                uint32_t b0 = f2b(B[br * LDA + bc]);
                uint32_t b1 = f2b(B[br * LDA + bc + 4]);
                mma_tf32(acc[0][nf], a[0], b0, b1);
                mma_tf32(acc[1][nf], a[1], b0, b1);
            }
        }
        __syncthreads();
    }

    float* out; int mloc;
    if (m0 < 65536) { out = g_xg0; mloc = m0; } else { out = g_xg1; mloc = m0 - 65536; }
#pragma unroll
    for (int mf = 0; mf < 2; mf++)
#pragma unroll
        for (int nf = 0; nf < 8; nf++) {
            int r = mloc + wm * 32 + mf * 16 + (lane >> 2);
            int c = n0 + wn * 64 + nf * 8 + (lane & 3) * 2;
            float bi0 = bW[c] + bU[c];
            float bi1 = bW[c + 1] + bU[c + 1];
            out[(size_t)r * GDIM + c]           = acc[mf][nf][0] + bi0;
            out[(size_t)r * GDIM + c + 1]       = acc[mf][nf][1] + bi1;
            out[(size_t)(r + 8) * GDIM + c]     = acc[mf][nf][2] + bi0;
            out[(size_t)(r + 8) * GDIM + c + 1] = acc[mf][nf][3] + bi1;
        }
}

// ---------------- persistent recurrence kernel ----------------
// 128 CTAs, all co-resident. CTA n owns hidden cols [n*8, n*8+8). Its 32x1024
// Wh tile (4 gates x 8 cols) lives in SMEM (tf32) for all 1024 steps. c lives
// in registers. Per step: stream h (128x1024) through a double-buffered SMEM
// stage, 128x32 tf32 MMA, elementwise cell update, software grid barrier.
#define LDW 1028   // Wh smem row stride (mod 32 == 4 -> conflict-free B-frag LDS)
#define LDB 68     // h  smem row stride (mod 32 == 4 -> conflict-free A-frag LDS)
#define SM_WH (32 * LDW)            // 32896 floats = 131584 B
#define SM_AS (2 * 128 * LDB)       // 17408 floats =  69632 B
#define SMEM_STEP ((SM_WH + SM_AS) * 4)  // 201216 B

__global__ __launch_bounds__(256, 1) void lstm_persistent_kernel(const float* __restrict__ Wh) {
    extern __shared__ float sm[];
    float* Bw = sm;            // [32][LDW] persistent Wh tile (tf32)
    float* As = sm + SM_WH;    // 2 stages * [128][LDB] h staging; reused as G stash
    const int j0 = blockIdx.x * 8;
    const int tid = threadIdx.x, lane = tid & 31, wid = tid >> 5;

    // one-time: gather this CTA's 32 Wh rows (row q*1024 + j0+jj), tf32-round
    for (int idx = tid; idx < 32 * 1024; idx += 256) {
        int r = idx >> 10, c = idx & 1023;              // r = q*8 + jj
        int wr = (r >> 3) * HDIM + j0 + (r & 7);
        Bw[r * LDW + c] = tf32_rna(Wh[(size_t)wr * HDIM + c]);
    }
    float creg[4] = {0.0f, 0.0f, 0.0f, 0.0f};
    __syncthreads();

    for (int t = 0; t < S_LEN; t++) {
        const float* h_in  = (t & 1) ? g_h1 : g_h0;
        float*       h_out = (t & 1) ? g_h0 : g_h1;

        float acc[4][4];
#pragma unroll
        for (int a = 0; a < 4; a++)
#pragma unroll
            for (int b = 0; b < 4; b++) acc[a][b] = 0.0f;

        if (t > 0) {  // t==0: h==0 -> gates are xg only
            auto load = [&](int kb, int st) {
                float* Ad = As + st * 128 * LDB;
#pragma unroll
                for (int i = 0; i < 8; i++) {
                    int f = tid + i * 256, r = f >> 4, kq = f & 15;
                    cp16(Ad + r * LDB + kq * 4, h_in + r * HDIM + kb * 64 + kq * 4);
                }
                cp_commit();
            };
            load(0, 0);
            const int NKB = HDIM / 64;  // 16
            for (int kb = 0; kb < NKB; kb++) {
                int st = kb & 1;
                if (kb + 1 < NKB) { load(kb + 1, st ^ 1); cp_wait<1>(); }
                else              { cp_wait<0>(); }
                __syncthreads();
                const float* A = As + st * 128 * LDB;
#pragma unroll
                for (int k8 = 0; k8 < 8; k8++) {
                    int kk = k8 * 8;
                    int r  = wid * 16 + (lane >> 2);
                    int cA = kk + (lane & 3);
                    uint32_t a[4];
                    a[0] = f2b(A[r * LDB + cA]);
                    a[1] = f2b(A[(r + 8) * LDB + cA]);
                    a[2] = f2b(A[r * LDB + cA + 4]);
                    a[3] = f2b(A[(r + 8) * LDB + cA + 4]);
                    int cB = kb * 64 + kk + (lane & 3);
#pragma unroll
                    for (int nf = 0; nf < 4; nf++) {
                        int br = nf * 8 + (lane >> 2);
                        uint32_t b0 = f2b(Bw[br * LDW + cB]);
                        uint32_t b1 = f2b(Bw[br * LDW + cB + 4]);
                        mma_tf32(acc[nf], a, b0, b1);
                    }
                }
                __syncthreads();
            }
        }

        // stash gate tile (h@Wh part) into smem (reuse As region)
        float* G = As;  // [128][33]
#pragma unroll
        for (int nf = 0; nf < 4; nf++) {
            int r = wid * 16 + (lane >> 2);
            int c = nf * 8 + (lane & 3) * 2;
            G[r * 33 + c]           = acc[nf][0];
            G[r * 33 + c + 1]       = acc[nf][1];
            G[(r + 8) * 33 + c]     = acc[nf][2];
            G[(r + 8) * 33 + c + 1] = acc[nf][3];
        }
        __syncthreads();

        // elementwise LSTM cell update for this CTA's 128 x 8 block, c in regs
#pragma unroll
        for (int i = 0; i < 4; i++) {
            int e = tid + i * 256;
            int b = e >> 3, jj = e & 7;
            const float* xgp; int mloc;
            if (b < 64) { xgp = g_xg0; mloc = b * 1024 + t; }
            else        { xgp = g_xg1; mloc = (b - 64) * 1024 + t; }
            size_t xb = (size_t)mloc * GDIM + j0 + jj;
            float fg = G[b * 33 + jj]      + xgp[xb];
            float ig = G[b * 33 + 8 + jj]  + xgp[xb + 1024];
            float gg = G[b * 33 + 16 + jj] + xgp[xb + 2048];
            float og = G[b * 33 + 24 + jj] + xgp[xb + 3072];
            float cn = sigf(fg) * creg[i] + sigf(ig) * tanhf(gg);
            creg[i] = cn;
            // pre-round: next step's A operand is consumed as tf32 anyway
            h_out[b * HDIM + j0 + jj] = tf32_rna(sigf(og) * tanhf(cn));
        }

        grid_barrier();
    }
}

// ---------------- FC head: out = hT @ fc_w^T + fc_b ----------------
__global__ void fc_kernel(const float* __restrict__ fc_w,
                          const float* __restrict__ fc_b,
                          float* __restrict__ out) {
    __shared__ float hrow[HDIM];
    int b = blockIdx.x, o = threadIdx.x;
    for (int k = o; k < HDIM; k += 128) hrow[k] = g_h0[b * HDIM + k];
    __syncthreads();
    const float* w = fc_w + (size_t)o * HDIM;
    float acc = fc_b[o];
#pragma unroll 8
    for (int k = 0; k < HDIM; k++) acc += hrow[k] * w[k];
    out[b * ODIM + o] = acc;
}

// ---------------- launch ----------------
extern "C" void kernel_launch(void* const* d_in, const int* in_sizes, int n_in,
                              void* d_out, int out_size) {
    const float* x    = (const float*)d_in[0];
    const float* Wx   = (const float*)d_in[1];
    const float* bW   = (const float*)d_in[2];
    const float* Wh   = (const float*)d_in[3];
    const float* bU   = (const float*)d_in[4];
    const float* fc_w = (const float*)d_in[5];
    const float* fc_b = (const float*)d_in[6];
    float* out = (float*)d_out;

    // opt-in to >48KB dynamic smem (state change, idempotent, no allocation)
    cudaFuncSetAttribute(gemm_xg_kernel, cudaFuncAttributeMaxDynamicSharedMemorySize, 73728);
    cudaFuncSetAttribute(lstm_persistent_kernel, cudaFuncAttributeMaxDynamicSharedMemorySize, SMEM_STEP);

    prep_kernel<<<67584, 256>>>(x, Wx);
    gemm_xg_kernel<<<dim3(32, 1024), 256, 73728>>>(bW, bU);
    lstm_persistent_kernel<<<NCTA, 256, SMEM_STEP>>>(Wh);
    fc_kernel<<<128, 128>>>(fc_w, fc_b, out);
}

// round 9
// speedup vs baseline: 2.3039x; 1.5803x over previous
#include <cuda_runtime.h>
#include <cuda_fp16.h>
#include <cstdint>
#include <math.h>

// LSTM: B=128, S=1024, I=512, H=1024, O=128
#define S_LEN 1024
#define BATCH 128
#define IDIM  512
#define HDIM  1024
#define GDIM  4096
#define ODIM  128
#define NCTA  128

// ---------------- scratch (static device allocations; no cudaMalloc) ----------------
__device__ float  g_x  [(size_t)BATCH * S_LEN * IDIM];   // tf32-rounded copy of x
__device__ float  g_Wx [(size_t)GDIM * IDIM];            // tf32-rounded Wx
__device__ float  g_xg0[(size_t)65536 * GDIM];           // xg rows m <  65536
__device__ float  g_xg1[(size_t)65536 * GDIM];           // xg rows m >= 65536
__device__ __half g_h0 [BATCH * HDIM];                   // hidden state (fp16), ping
__device__ __half g_h1 [BATCH * HDIM];                   // hidden state (fp16), pong
__device__ unsigned g_bar;                               // monotone grid-barrier counter

// ---------------- generic helpers ----------------
__device__ __forceinline__ uint32_t f2b(float x) { return __float_as_uint(x); }

__device__ __forceinline__ float tf32_rna(float v) {
    uint32_t u;
    asm("cvt.rna.tf32.f32 %0, %1;" : "=r"(u) : "f"(v));
    return __uint_as_float(u);
}

__device__ __forceinline__ uint32_t smem_u32(const void* p) {
    return (uint32_t)__cvta_generic_to_shared(p);
}

__device__ __forceinline__ void cp16(uint32_t sptr, const void* gptr) {
    asm volatile("cp.async.cg.shared.global [%0], [%1], 16;\n" :: "r"(sptr), "l"(gptr));
}
__device__ __forceinline__ void cp16p(void* sptr, const void* gptr) {
    cp16(smem_u32(sptr), gptr);
}
__device__ __forceinline__ void cp_commit() { asm volatile("cp.async.commit_group;\n"); }
template <int N> __device__ __forceinline__ void cp_wait() {
    asm volatile("cp.async.wait_group %0;\n" :: "n"(N));
}

// tf32 warp mma (xg GEMM, proven)
__device__ __forceinline__ void mma_tf32(float* d, const uint32_t* a, uint32_t b0, uint32_t b1) {
    asm volatile(
        "mma.sync.aligned.m16n8k8.row.col.f32.tf32.tf32.f32 "
        "{%0,%1,%2,%3},{%4,%5,%6,%7},{%8,%9},{%0,%1,%2,%3};\n"
        : "+f"(d[0]), "+f"(d[1]), "+f"(d[2]), "+f"(d[3])
        : "r"(a[0]), "r"(a[1]), "r"(a[2]), "r"(a[3]), "r"(b0), "r"(b1));
}

// fp16 warp mma, fp32 accumulate (recurrence)
__device__ __forceinline__ void mma_f16(float* d, const uint32_t* a, uint32_t b0, uint32_t b1) {
    asm volatile(
        "mma.sync.aligned.m16n8k16.row.col.f32.f16.f16.f32 "
        "{%0,%1,%2,%3},{%4,%5,%6,%7},{%8,%9},{%0,%1,%2,%3};\n"
        : "+f"(d[0]), "+f"(d[1]), "+f"(d[2]), "+f"(d[3])
        : "r"(a[0]), "r"(a[1]), "r"(a[2]), "r"(a[3]), "r"(b0), "r"(b1));
}

__device__ __forceinline__ void ldmx4(uint32_t* r, uint32_t addr) {
    asm volatile("ldmatrix.sync.aligned.m8n8.x4.shared.b16 {%0,%1,%2,%3}, [%4];"
                 : "=r"(r[0]), "=r"(r[1]), "=r"(r[2]), "=r"(r[3]) : "r"(addr));
}

__device__ __forceinline__ float sigf(float x) { return 1.0f / (1.0f + expf(-x)); }

// Software grid barrier (monotone counter; all NCTA CTAs co-resident at 1 CTA/SM)
__device__ __forceinline__ void grid_barrier() {
    __threadfence();
    __syncthreads();
    if (threadIdx.x == 0) {
        unsigned ticket = atomicAdd(&g_bar, 1u) + 1u;
        unsigned target = (ticket + (NCTA - 1u)) & ~(NCTA - 1u);
        unsigned v;
        do { v = *((volatile unsigned*)&g_bar); } while ((int)(v - target) < 0);
    }
    __syncthreads();
}

// ---------------- prep: round x, Wx to tf32 once per call ----------------
__global__ void prep_kernel(const float* __restrict__ x,
                            const float* __restrict__ Wx) {
    const size_t NX  = (size_t)BATCH * S_LEN * IDIM / 4;
    const size_t NWX = (size_t)GDIM * IDIM / 4;
    size_t i = (size_t)blockIdx.x * blockDim.x + threadIdx.x;
    if (i >= NX + NWX) return;
    const float4* src; float4* dst; size_t j;
    if (i < NX) { src = (const float4*)x;  dst = (float4*)g_x;  j = i; }
    else        { src = (const float4*)Wx; dst = (float4*)g_Wx; j = i - NX; }
    float4 v = src[j];
    v.x = tf32_rna(v.x); v.y = tf32_rna(v.y);
    v.z = tf32_rna(v.z); v.w = tf32_rna(v.w);
    dst[j] = v;
}

// ---------------- kernel A: xg = x @ Wx^T + (bW + bU) (unchanged, proven) ----------------
#define LDA 36
__global__ __launch_bounds__(256) void gemm_xg_kernel(const float* __restrict__ bW,
                                                      const float* __restrict__ bU) {
    extern __shared__ float sm[];
    float* As = sm;
    float* Bs = sm + 2 * 128 * LDA;
    const int n0 = blockIdx.x * 128;
    const int m0 = blockIdx.y * 128;
    const float* Ag = g_x  + (size_t)m0 * IDIM;
    const float* Bg = g_Wx + (size_t)n0 * IDIM;
    const int tid = threadIdx.x, lane = tid & 31, wid = tid >> 5;
    const int wm = wid >> 1, wn = wid & 1;

    float acc[2][8][4];
#pragma unroll
    for (int a = 0; a < 2; a++)
#pragma unroll
        for (int b = 0; b < 8; b++)
#pragma unroll
            for (int c = 0; c < 4; c++) acc[a][b][c] = 0.0f;

    auto load = [&](int kb, int st) {
        float* Ad = As + st * 128 * LDA;
        float* Bd = Bs + st * 128 * LDA;
#pragma unroll
        for (int i = 0; i < 4; i++) {
            int f = tid + i * 256, r = f >> 3, kq = f & 7;
            cp16p(Ad + r * LDA + kq * 4, Ag + (size_t)r * IDIM + kb * 32 + kq * 4);
        }
#pragma unroll
        for (int i = 0; i < 4; i++) {
            int f = tid + i * 256, r = f >> 3, kq = f & 7;
            cp16p(Bd + r * LDA + kq * 4, Bg + (size_t)r * IDIM + kb * 32 + kq * 4);
        }
        cp_commit();
    };

    load(0, 0);
    const int NKB = IDIM / 32;
    for (int kb = 0; kb < NKB; kb++) {
        int st = kb & 1;
        if (kb + 1 < NKB) { load(kb + 1, st ^ 1); cp_wait<1>(); }
        else              { cp_wait<0>(); }
        __syncthreads();
        const float* A = As + st * 128 * LDA;
        const float* B = Bs + st * 128 * LDA;
#pragma unroll
        for (int k8 = 0; k8 < 4; k8++) {
            int kk = k8 * 8;
            uint32_t a[2][4];
#pragma unroll
            for (int mf = 0; mf < 2; mf++) {
                int r = wm * 32 + mf * 16 + (lane >> 2);
                int c = kk + (lane & 3);
                a[mf][0] = f2b(A[r * LDA + c]);
                a[mf][1] = f2b(A[(r + 8) * LDA + c]);
                a[mf][2] = f2b(A[r * LDA + c + 4]);
                a[mf][3] = f2b(A[(r + 8) * LDA + c + 4]);
            }
#pragma unroll
            for (int nf = 0; nf < 8; nf++) {
                int br = wn * 64 + nf * 8 + (lane >> 2);
                int bc = kk + (lane & 3);
                uint32_t b0 = f2b(B[br * LDA + bc]);
                uint32_t b1 = f2b(B[br * LDA + bc + 4]);
                mma_tf32(acc[0][nf], a[0], b0, b1);
                mma_tf32(acc[1][nf], a[1], b0, b1);
            }
        }
        __syncthreads();
    }

    float* out; int mloc;
    if (m0 < 65536) { out = g_xg0; mloc = m0; } else { out = g_xg1; mloc = m0 - 65536; }
#pragma unroll
    for (int mf = 0; mf < 2; mf++)
#pragma unroll
        for (int nf = 0; nf < 8; nf++) {
            int r = mloc + wm * 32 + mf * 16 + (lane >> 2);
            int c = n0 + wn * 64 + nf * 8 + (lane & 3) * 2;
            float bi0 = bW[c] + bU[c];
            float bi1 = bW[c + 1] + bU[c + 1];
            out[(size_t)r * GDIM + c]           = acc[mf][nf][0] + bi0;
            out[(size_t)r * GDIM + c + 1]       = acc[mf][nf][1] + bi1;
            out[(size_t)(r + 8) * GDIM + c]     = acc[mf][nf][2] + bi0;
            out[(size_t)(r + 8) * GDIM + c + 1] = acc[mf][nf][3] + bi1;
        }
}

// ---------------- persistent fp16 HMMA recurrence kernel ----------------
// CTA n owns hidden cols [n*8, n*8+8) -> 32 gate cols (4 gates x 8). Per step:
// D[128x32] = h[128x1024] @ Wh_tile^T via ldmatrix + mma.m16n8k16 (fp16 in, fp32 acc).
// Warp w owns batch rows [w*16, w*16+16). Wh tile (32x1024 fp16) resident in SMEM.
// h streamed as 8 chunks of [128x128] fp16 (2 cp.async buffers). D-fragment layout
// maps each thread to (2 rows x 2 cols x 4 gates) -> epilogue fully in registers,
// c state in 4 regs/thread, h written back as fp16.
//
// SMEM layout (bytes):
//   Wh tile: 32 rows, stride 2064 B (1032 fp16; 2064%128==16 -> conflict-free ldmatrix)
//   A bufs : 2 x [128 rows, stride 272 B (136 fp16; 272%128==16)]
#define WH_STRIDE 1032                   // fp16 units
#define A_STRIDE  136                    // fp16 units
#define OFF_WH    0
#define WH_BYTES  (32 * WH_STRIDE * 2)   // 66048
#define OFF_A0    WH_BYTES
#define A_BUF_BYTES (128 * A_STRIDE * 2) // 34816
#define SMEM_REC  (OFF_A0 + 2 * A_BUF_BYTES)  // 135680

__global__ __launch_bounds__(256, 1) void lstm_rec_kernel(const float* __restrict__ Wh) {
    extern __shared__ char smc[];
    __half* Bw = (__half*)(smc + OFF_WH);
    const uint32_t smem_base = smem_u32(smc);
    const int tid = threadIdx.x, lane = tid & 31, wid = tid >> 5;
    const int j0 = blockIdx.x * 8;

    // one-time: Wh tile rows rB = q*8+jj  <-  Wh row q*1024 + j0 + jj, fp16-rounded
    for (int idx = tid; idx < 32 * 1024; idx += 256) {
        int rB = idx >> 10, c = idx & 1023;
        int wr = (rB >> 3) * HDIM + j0 + (rB & 7);
        Bw[rB * WH_STRIDE + c] = __float2half(Wh[(size_t)wr * HDIM + c]);
    }
    __syncthreads();

    // this thread's output coordinates
    const int b0 = wid * 16 + (lane >> 2);   // batch row (and b0+8)
    const int jc = 2 * (lane & 3);           // hidden col pair within CTA's 8
    // xg base pointers for rows b0 and b0+8 (per-gate stride GDIM/4 = 1024)
    const float* xg_base0 = (b0 < 64 ? g_xg0 : g_xg1) +
        (size_t)((b0 & 63) * 1024) * GDIM + j0 + jc;
    const float* xg_base1 = ((b0 + 8) < 64 ? g_xg0 : g_xg1) +
        (size_t)(((b0 + 8) & 63) * 1024) * GDIM + j0 + jc;

    // ldmatrix source addresses (lane-dependent parts precomputed)
    // A: rows wid*16 + (lane&15), k offset += ((lane>>4)<<3)
    const int a_row = wid * 16 + (lane & 15);
    const int a_koff = (lane >> 4) << 3;
    // B: Wh rows (g2*2 + (lane>>4))*8 + (lane&7), k offset += (lane&8)
    const int b_rowoff = ((lane >> 4) << 3) + (lane & 7);   // + g2*16
    const int b_koff = lane & 8;

    float creg[4] = {0.0f, 0.0f, 0.0f, 0.0f};   // c state: [row-half][col e]

    for (int t = 0; t < S_LEN; t++) {
        const __half* h_in  = (t & 1) ? g_h1 : g_h0;
        __half*       h_out = (t & 1) ? g_h0 : g_h1;

        // prefetch xg for this thread (2 rows x 4 gates x 2 cols)
        float2 xv0[4], xv1[4];
        const float* xr0 = xg_base0 + (size_t)t * GDIM;
        const float* xr1 = xg_base1 + (size_t)t * GDIM;
#pragma unroll
        for (int q = 0; q < 4; q++) {
            xv0[q] = *(const float2*)(xr0 + q * 1024);
            xv1[q] = *(const float2*)(xr1 + q * 1024);
        }

        float acc[4][4];
#pragma unroll
        for (int a = 0; a < 4; a++)
#pragma unroll
            for (int b = 0; b < 4; b++) acc[a][b] = 0.0f;

        if (t > 0) {
            // chunk loader: [128 x 128] fp16 into buffer s
            auto load_chunk = [&](int kb, int s) {
                uint32_t base = smem_base + OFF_A0 + s * A_BUF_BYTES;
#pragma unroll
                for (int i = 0; i < 8; i++) {
                    int f = tid + i * 256;
                    int r = f >> 4, seg = f & 15;
                    cp16(base + r * (A_STRIDE * 2) + seg * 16,
                         h_in + r * HDIM + kb * 128 + seg * 8);
                }
                cp_commit();
            };

            load_chunk(0, 0);
            for (int kb = 0; kb < 8; kb++) {
                int s = kb & 1;
                if (kb < 7) { load_chunk(kb + 1, s ^ 1); cp_wait<1>(); }
                else        { cp_wait<0>(); }
                __syncthreads();   // chunk kb resident; prev compute on s^1 done

                uint32_t a_addr = smem_base + OFF_A0 + s * A_BUF_BYTES +
                                  a_row * (A_STRIDE * 2) + a_koff * 2;
                uint32_t b_addr0 = smem_base + OFF_WH +
                                   b_rowoff * (WH_STRIDE * 2) +
                                   (kb * 128 + b_koff) * 2;
#pragma unroll
                for (int k16 = 0; k16 < 8; k16++) {
                    uint32_t af[4], bf0[4], bf1[4];
                    ldmx4(af, a_addr + k16 * 32);                       // 16 fp16 = 32B
                    ldmx4(bf0, b_addr0 + k16 * 32);                     // gates f,i
                    ldmx4(bf1, b_addr0 + 16 * (WH_STRIDE * 2) + k16 * 32); // gates g,o
                    mma_f16(acc[0], af, bf0[0], bf0[1]);
                    mma_f16(acc[1], af, bf0[2], bf0[3]);
                    mma_f16(acc[2], af, bf1[0], bf1[1]);
                    mma_f16(acc[3], af, bf1[2], bf1[3]);
                }
                __syncthreads();   // all warps done reading buf s
            }
        }

        // elementwise LSTM cell update, all in registers
        // acc[q][0..1] = row b0 cols jc,jc+1 ; acc[q][2..3] = row b0+8
        {
            float h00, h01, h10, h11;
            {
                float f = acc[0][0] + xv0[0].x, i = acc[1][0] + xv0[1].x;
                float g = acc[2][0] + xv0[2].x, o = acc[3][0] + xv0[3].x;
                float cn = sigf(f) * creg[0] + sigf(i) * tanhf(g);
                creg[0] = cn; h00 = sigf(o) * tanhf(cn);
            }
            {
                float f = acc[0][1] + xv0[0].y, i = acc[1][1] + xv0[1].y;
                float g = acc[2][1] + xv0[2].y, o = acc[3][1] + xv0[3].y;
                float cn = sigf(f) * creg[1] + sigf(i) * tanhf(g);
                creg[1] = cn; h01 = sigf(o) * tanhf(cn);
            }
            {
                float f = acc[0][2] + xv1[0].x, i = acc[1][2] + xv1[1].x;
                float g = acc[2][2] + xv1[2].x, o = acc[3][2] + xv1[3].x;
                float cn = sigf(f) * creg[2] + sigf(i) * tanhf(g);
                creg[2] = cn; h10 = sigf(o) * tanhf(cn);
            }
            {
                float f = acc[0][3] + xv1[0].y, i = acc[1][3] + xv1[1].y;
                float g = acc[2][3] + xv1[2].y, o = acc[3][3] + xv1[3].y;
                float cn = sigf(f) * creg[3] + sigf(i) * tanhf(g);
                creg[3] = cn; h11 = sigf(o) * tanhf(cn);
            }
            *(__half2*)(h_out + b0 * HDIM + j0 + jc)       = __floats2half2_rn(h00, h01);
            *(__half2*)(h_out + (b0 + 8) * HDIM + j0 + jc) = __floats2half2_rn(h10, h11);
        }

        grid_barrier();
    }
}

// ---------------- FC head: out = hT @ fc_w^T + fc_b ----------------
__global__ void fc_kernel(const float* __restrict__ fc_w,
                          const float* __restrict__ fc_b,
                          float* __restrict__ out) {
    __shared__ float hrow[HDIM];
    int b = blockIdx.x, o = threadIdx.x;
    for (int k = o; k < HDIM; k += 128) hrow[k] = __half2float(g_h0[b * HDIM + k]);
    __syncthreads();
    const float* w = fc_w + (size_t)o * HDIM;
    float acc = fc_b[o];
#pragma unroll 8
    for (int k = 0; k < HDIM; k++) acc += hrow[k] * w[k];
    out[b * ODIM + o] = acc;
}

// ---------------- launch ----------------
extern "C" void kernel_launch(void* const* d_in, const int* in_sizes, int n_in,
                              void* d_out, int out_size) {
    const float* x    = (const float*)d_in[0];
    const float* Wx   = (const float*)d_in[1];
    const float* bW   = (const float*)d_in[2];
    const float* Wh   = (const float*)d_in[3];
    const float* bU   = (const float*)d_in[4];
    const float* fc_w = (const float*)d_in[5];
    const float* fc_b = (const float*)d_in[6];
    float* out = (float*)d_out;

    // opt-in to >48KB dynamic smem (state change, idempotent, no allocation)
    cudaFuncSetAttribute(gemm_xg_kernel, cudaFuncAttributeMaxDynamicSharedMemorySize, 73728);
    cudaFuncSetAttribute(lstm_rec_kernel, cudaFuncAttributeMaxDynamicSharedMemorySize, SMEM_REC);

    prep_kernel<<<67584, 256>>>(x, Wx);
    gemm_xg_kernel<<<dim3(32, 1024), 256, 73728>>>(bW, bU);
    lstm_rec_kernel<<<NCTA, 256, SMEM_REC>>>(Wh);
    fc_kernel<<<128, 128>>>(fc_w, fc_b, out);
}

// round 11
// speedup vs baseline: 2.3551x; 1.0222x over previous
#include <cuda_runtime.h>
#include <cuda_fp16.h>
#include <cstdint>
#include <math.h>

// LSTM: B=128, S=1024, I=512, H=1024, O=128
#define S_LEN 1024
#define BATCH 128
#define IDIM  512
#define HDIM  1024
#define GDIM  4096
#define ODIM  128
#define NCTA  128

// ---------------- scratch (static device allocations; no cudaMalloc) ----------------
__device__ float  g_x  [(size_t)BATCH * S_LEN * IDIM];   // tf32-rounded copy of x
__device__ float  g_Wx [(size_t)GDIM * IDIM];            // tf32-rounded Wx
__device__ float  g_xg0[(size_t)65536 * GDIM];           // xg rows m <  65536
__device__ float  g_xg1[(size_t)65536 * GDIM];           // xg rows m >= 65536
__device__ __half g_h0 [BATCH * HDIM];                   // hidden state (fp16), ping
__device__ __half g_h1 [BATCH * HDIM];                   // hidden state (fp16), pong
__device__ unsigned g_bar;                               // monotone grid-barrier counter

// ---------------- generic helpers ----------------
__device__ __forceinline__ uint32_t f2b(float x) { return __float_as_uint(x); }

__device__ __forceinline__ float tf32_rna(float v) {
    uint32_t u;
    asm("cvt.rna.tf32.f32 %0, %1;" : "=r"(u) : "f"(v));
    return __uint_as_float(u);
}

__device__ __forceinline__ uint32_t smem_u32(const void* p) {
    return (uint32_t)__cvta_generic_to_shared(p);
}

__device__ __forceinline__ void cp16(uint32_t sptr, const void* gptr) {
    asm volatile("cp.async.cg.shared.global [%0], [%1], 16;\n" :: "r"(sptr), "l"(gptr));
}
__device__ __forceinline__ void cp16p(void* sptr, const void* gptr) {
    cp16(smem_u32(sptr), gptr);
}
__device__ __forceinline__ void cp_commit() { asm volatile("cp.async.commit_group;\n"); }
template <int N> __device__ __forceinline__ void cp_wait() {
    asm volatile("cp.async.wait_group %0;\n" :: "n"(N));
}

// tf32 warp mma (xg GEMM, proven)
__device__ __forceinline__ void mma_tf32(float* d, const uint32_t* a, uint32_t b0, uint32_t b1) {
    asm volatile(
        "mma.sync.aligned.m16n8k8.row.col.f32.tf32.tf32.f32 "
        "{%0,%1,%2,%3},{%4,%5,%6,%7},{%8,%9},{%0,%1,%2,%3};\n"
        : "+f"(d[0]), "+f"(d[1]), "+f"(d[2]), "+f"(d[3])
        : "r"(a[0]), "r"(a[1]), "r"(a[2]), "r"(a[3]), "r"(b0), "r"(b1));
}

// fp16 warp mma, fp32 accumulate (recurrence)
__device__ __forceinline__ void mma_f16(float* d, const uint32_t* a, uint32_t b0, uint32_t b1) {
    asm volatile(
        "mma.sync.aligned.m16n8k16.row.col.f32.f16.f16.f32 "
        "{%0,%1,%2,%3},{%4,%5,%6,%7},{%8,%9},{%0,%1,%2,%3};\n"
        : "+f"(d[0]), "+f"(d[1]), "+f"(d[2]), "+f"(d[3])
        : "r"(a[0]), "r"(a[1]), "r"(a[2]), "r"(a[3]), "r"(b0), "r"(b1));
}

__device__ __forceinline__ void ldmx4(uint32_t* r, uint32_t addr) {
    asm volatile("ldmatrix.sync.aligned.m8n8.x4.shared.b16 {%0,%1,%2,%3}, [%4];"
                 : "=r"(r[0]), "=r"(r[1]), "=r"(r[2]), "=r"(r[3]) : "r"(addr));
}

__device__ __forceinline__ float sigf(float x) { return 1.0f / (1.0f + expf(-x)); }

// fast transcendentals for the recurrence epilogue (MUFU.EX2-based; rel err ~1e-6,
// invisible under the fp16/tf32 rounding already in the pipeline)
__device__ __forceinline__ float sig_fast(float x) {
    x = fminf(fmaxf(x, -30.0f), 30.0f);
    return __fdividef(1.0f, 1.0f + __expf(-x));
}
__device__ __forceinline__ float tanh_fast(float x) {
    x = fminf(fmaxf(x, -15.0f), 15.0f);
    float e = __expf(-2.0f * x);
    return __fdividef(1.0f - e, 1.0f + e);
}

// Software grid barrier (monotone counter; all NCTA CTAs co-resident at 1 CTA/SM)
__device__ __forceinline__ void grid_barrier() {
    __threadfence();
    __syncthreads();
    if (threadIdx.x == 0) {
        unsigned ticket = atomicAdd(&g_bar, 1u) + 1u;
        unsigned target = (ticket + (NCTA - 1u)) & ~(NCTA - 1u);
        unsigned v;
        do { v = *((volatile unsigned*)&g_bar); } while ((int)(v - target) < 0);
    }
    __syncthreads();
}

// ---------------- prep: round x, Wx to tf32 once per call ----------------
__global__ void prep_kernel(const float* __restrict__ x,
                            const float* __restrict__ Wx) {
    const size_t NX  = (size_t)BATCH * S_LEN * IDIM / 4;
    const size_t NWX = (size_t)GDIM * IDIM / 4;
    size_t i = (size_t)blockIdx.x * blockDim.x + threadIdx.x;
    if (i >= NX + NWX) return;
    const float4* src; float4* dst; size_t j;
    if (i < NX) { src = (const float4*)x;  dst = (float4*)g_x;  j = i; }
    else        { src = (const float4*)Wx; dst = (float4*)g_Wx; j = i - NX; }
    float4 v = src[j];
    v.x = tf32_rna(v.x); v.y = tf32_rna(v.y);
    v.z = tf32_rna(v.z); v.w = tf32_rna(v.w);
    dst[j] = v;
}

// ---------------- kernel A: xg = x @ Wx^T + (bW + bU) (unchanged, proven) ----------------
#define LDA 36
__global__ __launch_bounds__(256) void gemm_xg_kernel(const float* __restrict__ bW,
                                                      const float* __restrict__ bU) {
    extern __shared__ float sm[];
    float* As = sm;
    float* Bs = sm + 2 * 128 * LDA;
    const int n0 = blockIdx.x * 128;
    const int m0 = blockIdx.y * 128;
    const float* Ag = g_x  + (size_t)m0 * IDIM;
    const float* Bg = g_Wx + (size_t)n0 * IDIM;
    const int tid = threadIdx.x, lane = tid & 31, wid = tid >> 5;
    const int wm = wid >> 1, wn = wid & 1;

    float acc[2][8][4];
#pragma unroll
    for (int a = 0; a < 2; a++)
#pragma unroll
        for (int b = 0; b < 8; b++)
#pragma unroll
            for (int c = 0; c < 4; c++) acc[a][b][c] = 0.0f;

    auto load = [&](int kb, int st) {
        float* Ad = As + st * 128 * LDA;
        float* Bd = Bs + st * 128 * LDA;
#pragma unroll
        for (int i = 0; i < 4; i++) {
            int f = tid + i * 256, r = f >> 3, kq = f & 7;
            cp16p(Ad + r * LDA + kq * 4, Ag + (size_t)r * IDIM + kb * 32 + kq * 4);
        }
#pragma unroll
        for (int i = 0; i < 4; i++) {
            int f = tid + i * 256, r = f >> 3, kq = f & 7;
            cp16p(Bd + r * LDA + kq * 4, Bg + (size_t)r * IDIM + kb * 32 + kq * 4);
        }
        cp_commit();
    };

    load(0, 0);
    const int NKB = IDIM / 32;
    for (int kb = 0; kb < NKB; kb++) {
        int st = kb & 1;
        if (kb + 1 < NKB) { load(kb + 1, st ^ 1); cp_wait<1>(); }
        else              { cp_wait<0>(); }
        __syncthreads();
        const float* A = As + st * 128 * LDA;
        const float* B = Bs + st * 128 * LDA;
#pragma unroll
        for (int k8 = 0; k8 < 4; k8++) {
            int kk = k8 * 8;
            uint32_t a[2][4];
#pragma unroll
            for (int mf = 0; mf < 2; mf++) {
                int r = wm * 32 + mf * 16 + (lane >> 2);
                int c = kk + (lane & 3);
                a[mf][0] = f2b(A[r * LDA + c]);
                a[mf][1] = f2b(A[(r + 8) * LDA + c]);
                a[mf][2] = f2b(A[r * LDA + c + 4]);
                a[mf][3] = f2b(A[(r + 8) * LDA + c + 4]);
            }
#pragma unroll
            for (int nf = 0; nf < 8; nf++) {
                int br = wn * 64 + nf * 8 + (lane >> 2);
                int bc = kk + (lane & 3);
                uint32_t b0 = f2b(B[br * LDA + bc]);
                uint32_t b1 = f2b(B[br * LDA + bc + 4]);
                mma_tf32(acc[0][nf], a[0], b0, b1);
                mma_tf32(acc[1][nf], a[1], b0, b1);
            }
        }
        __syncthreads();
    }

    float* out; int mloc;
    if (m0 < 65536) { out = g_xg0; mloc = m0; } else { out = g_xg1; mloc = m0 - 65536; }
#pragma unroll
    for (int mf = 0; mf < 2; mf++)
#pragma unroll
        for (int nf = 0; nf < 8; nf++) {
            int r = mloc + wm * 32 + mf * 16 + (lane >> 2);
            int c = n0 + wn * 64 + nf * 8 + (lane & 3) * 2;
            float bi0 = bW[c] + bU[c];
            float bi1 = bW[c + 1] + bU[c + 1];
            out[(size_t)r * GDIM + c]           = acc[mf][nf][0] + bi0;
            out[(size_t)r * GDIM + c + 1]       = acc[mf][nf][1] + bi1;
            out[(size_t)(r + 8) * GDIM + c]     = acc[mf][nf][2] + bi0;
            out[(size_t)(r + 8) * GDIM + c + 1] = acc[mf][nf][3] + bi1;
        }
}

// ---------------- persistent fp16 HMMA recurrence kernel ----------------
// CTA n owns hidden cols [n*8, n*8+8) -> 32 gate cols (4 gates x 8). Per step:
// D[128x32] = h[128x1024] @ Wh_tile^T via ldmatrix + mma.m16n8k16 (fp16 in, fp32 acc).
// Warp w owns batch rows [w*16, w*16+16). Wh tile (32x1024 fp16) resident in SMEM.
// h streamed as 8 chunks of [128x128] fp16 through a 4-buffer / depth-3 cp.async
// pipeline with ONE __syncthreads per chunk (the post-wait sync also proves the
// buffer being refilled is no longer read). Epilogue fully in registers, c state
// in 4 regs/thread, fast MUFU-based transcendentals.
#define WH_STRIDE 1032                   // fp16 units (2064 B; %128==16 -> conflict-free)
#define A_STRIDE  136                    // fp16 units (272 B;  %128==16 -> conflict-free)
#define OFF_WH    0
#define WH_BYTES  (32 * WH_STRIDE * 2)   // 66048
#define OFF_A0    WH_BYTES
#define A_BUF_BYTES (128 * A_STRIDE * 2) // 34816
#define NBUF      4
#define SMEM_REC  (OFF_A0 + NBUF * A_BUF_BYTES)  // 205312

__global__ __launch_bounds__(256, 1) void lstm_rec_kernel(const float* __restrict__ Wh) {
    extern __shared__ char smc[];
    __half* Bw = (__half*)(smc + OFF_WH);
    const uint32_t smem_base = smem_u32(smc);
    const int tid = threadIdx.x, lane = tid & 31, wid = tid >> 5;
    const int j0 = blockIdx.x * 8;

    // one-time: Wh tile rows rB = q*8+jj  <-  Wh row q*1024 + j0 + jj, fp16-rounded
    for (int idx = tid; idx < 32 * 1024; idx += 256) {
        int rB = idx >> 10, c = idx & 1023;
        int wr = (rB >> 3) * HDIM + j0 + (rB & 7);
        Bw[rB * WH_STRIDE + c] = __float2half(Wh[(size_t)wr * HDIM + c]);
    }
    __syncthreads();

    // this thread's output coordinates
    const int b0 = wid * 16 + (lane >> 2);   // batch row (and b0+8)
    const int jc = 2 * (lane & 3);           // hidden col pair within CTA's 8
    const float* xg_base0 = (b0 < 64 ? g_xg0 : g_xg1) +
        (size_t)((b0 & 63) * 1024) * GDIM + j0 + jc;
    const float* xg_base1 = ((b0 + 8) < 64 ? g_xg0 : g_xg1) +
        (size_t)(((b0 + 8) & 63) * 1024) * GDIM + j0 + jc;

    // ldmatrix source address components (identical to the proven R8 layout)
    const int a_row = wid * 16 + (lane & 15);
    const int a_koff = (lane >> 4) << 3;
    const int b_rowoff = ((lane >> 4) << 3) + (lane & 7);   // + g2*16
    const int b_koff = lane & 8;

    float creg[4] = {0.0f, 0.0f, 0.0f, 0.0f};

    for (int t = 0; t < S_LEN; t++) {
        const __half* h_in  = (t & 1) ? g_h1 : g_h0;
        __half*       h_out = (t & 1) ? g_h0 : g_h1;

        // prefetch xg for this thread (2 rows x 4 gates x 2 cols)
        float2 xv0[4], xv1[4];
        const float* xr0 = xg_base0 + (size_t)t * GDIM;
        const float* xr1 = xg_base1 + (size_t)t * GDIM;
#pragma unroll
        for (int q = 0; q < 4; q++) {
            xv0[q] = *(const float2*)(xr0 + q * 1024);
            xv1[q] = *(const float2*)(xr1 + q * 1024);
        }

        float acc[4][4];
#pragma unroll
        for (int a = 0; a < 4; a++)
#pragma unroll
            for (int b = 0; b < 4; b++) acc[a][b] = 0.0f;

        if (t > 0) {
            // chunk loader: [128 x 128] fp16 into buffer s
            auto load_chunk = [&](int kb, int s) {
                uint32_t base = smem_base + OFF_A0 + s * A_BUF_BYTES;
#pragma unroll
                for (int i = 0; i < 8; i++) {
                    int f = tid + i * 256;
                    int r = f >> 4, seg = f & 15;
                    cp16(base + r * (A_STRIDE * 2) + seg * 16,
                         h_in + r * HDIM + kb * 128 + seg * 8);
                }
                cp_commit();
            };

            // depth-3 prefetch into 4 buffers
            load_chunk(0, 0);
            load_chunk(1, 1);
            load_chunk(2, 2);

            for (int kb = 0; kb < 8; kb++) {
                cp_wait<2>();        // chunk kb resident (groups complete in order)
                __syncthreads();     // also: all warps finished compute on chunk kb-1
                if (kb + 3 < 8) load_chunk(kb + 3, (kb + 3) & 3);
                else            cp_commit();   // empty group keeps wait<2> arithmetic

                int s = kb & 3;
                uint32_t a_addr = smem_base + OFF_A0 + s * A_BUF_BYTES +
                                  a_row * (A_STRIDE * 2) + a_koff * 2;
                uint32_t b_addr0 = smem_base + OFF_WH +
                                   b_rowoff * (WH_STRIDE * 2) +
                                   (kb * 128 + b_koff) * 2;
#pragma unroll
                for (int k16 = 0; k16 < 8; k16++) {
                    uint32_t af[4], bf0[4], bf1[4];
                    ldmx4(af, a_addr + k16 * 32);
                    ldmx4(bf0, b_addr0 + k16 * 32);                        // gates f,i
                    ldmx4(bf1, b_addr0 + 16 * (WH_STRIDE * 2) + k16 * 32); // gates g,o
                    mma_f16(acc[0], af, bf0[0], bf0[1]);
                    mma_f16(acc[1], af, bf0[2], bf0[3]);
                    mma_f16(acc[2], af, bf1[0], bf1[1]);
                    mma_f16(acc[3], af, bf1[2], bf1[3]);
                }
            }
        }

        // elementwise LSTM cell update, all in registers
        // acc[q][0..1] = row b0 cols jc,jc+1 ; acc[q][2..3] = row b0+8
        {
            float h00, h01, h10, h11;
            {
                float f = acc[0][0] + xv0[0].x, i = acc[1][0] + xv0[1].x;
                float g = acc[2][0] + xv0[2].x, o = acc[3][0] + xv0[3].x;
                float cn = sig_fast(f) * creg[0] + sig_fast(i) * tanh_fast(g);
                creg[0] = cn; h00 = sig_fast(o) * tanh_fast(cn);
            }
            {
                float f = acc[0][1] + xv0[0].y, i = acc[1][1] + xv0[1].y;
                float g = acc[2][1] + xv0[2].y, o = acc[3][1] + xv0[3].y;
                float cn = sig_fast(f) * creg[1] + sig_fast(i) * tanh_fast(g);
                creg[1] = cn; h01 = sig_fast(o) * tanh_fast(cn);
            }
            {
                float f = acc[0][2] + xv1[0].x, i = acc[1][2] + xv1[1].x;
                float g = acc[2][2] + xv1[2].x, o = acc[3][2] + xv1[3].x;
                float cn = sig_fast(f) * creg[2] + sig_fast(i) * tanh_fast(g);
                creg[2] = cn; h10 = sig_fast(o) * tanh_fast(cn);
            }
            {
                float f = acc[0][3] + xv1[0].y, i = acc[1][3] + xv1[1].y;
                float g = acc[2][3] + xv1[2].y, o = acc[3][3] + xv1[3].y;
                float cn = sig_fast(f) * creg[3] + sig_fast(i) * tanh_fast(g);
                creg[3] = cn; h11 = sig_fast(o) * tanh_fast(cn);
            }
            *(__half2*)(h_out + b0 * HDIM + j0 + jc)       = __floats2half2_rn(h00, h01);
            *(__half2*)(h_out + (b0 + 8) * HDIM + j0 + jc) = __floats2half2_rn(h10, h11);
        }

        grid_barrier();
    }
}

// ---------------- FC head: out = hT @ fc_w^T + fc_b ----------------
__global__ void fc_kernel(const float* __restrict__ fc_w,
                          const float* __restrict__ fc_b,
                          float* __restrict__ out) {
    __shared__ float hrow[HDIM];
    int b = blockIdx.x, o = threadIdx.x;
    for (int k = o; k < HDIM; k += 128) hrow[k] = __half2float(g_h0[b * HDIM + k]);
    __syncthreads();
    const float* w = fc_w + (size_t)o * HDIM;
    float acc = fc_b[o];
#pragma unroll 8
    for (int k = 0; k < HDIM; k++) acc += hrow[k] * w[k];
    out[b * ODIM + o] = acc;
}

// ---------------- launch ----------------
extern "C" void kernel_launch(void* const* d_in, const int* in_sizes, int n_in,
                              void* d_out, int out_size) {
    const float* x    = (const float*)d_in[0];
    const float* Wx   = (const float*)d_in[1];
    const float* bW   = (const float*)d_in[2];
    const float* Wh   = (const float*)d_in[3];
    const float* bU   = (const float*)d_in[4];
    const float* fc_w = (const float*)d_in[5];
    const float* fc_b = (const float*)d_in[6];
    float* out = (float*)d_out;

    // opt-in to >48KB dynamic smem (state change, idempotent, no allocation)
    cudaFuncSetAttribute(gemm_xg_kernel, cudaFuncAttributeMaxDynamicSharedMemorySize, 73728);
    cudaFuncSetAttribute(lstm_rec_kernel, cudaFuncAttributeMaxDynamicSharedMemorySize, SMEM_REC);

    prep_kernel<<<67584, 256>>>(x, Wx);
    gemm_xg_kernel<<<dim3(32, 1024), 256, 73728>>>(bW, bU);
    lstm_rec_kernel<<<NCTA, 256, SMEM_REC>>>(Wh);
    fc_kernel<<<128, 128>>>(fc_w, fc_b, out);
}